// round 3
// baseline (speedup 1.0000x reference)
#include <cuda_runtime.h>
#include <cstdint>

#define NG   1024
#define DIM  128
#define HID  512
#define MAXE 500000

// ---- scratch (no allocations allowed) ----
__device__ float    d_edge_mean[NG * DIM];   // final per-graph edge mean
__device__ float    d_nodesum[NG * DIM];     // per-graph node sums (red target)
__device__ unsigned d_ncnt[NG];              // node counts per graph
__device__ unsigned d_gcnt[NG];              // edge counts per graph
__device__ unsigned d_goff[NG];              // bucket start offsets
__device__ unsigned d_gpos[NG];              // running scatter positions
__device__ int      d_eg[MAXE];              // graph id per edge
__device__ int      d_bucket[MAXE];          // edge ids, grouped by graph
__device__ int      d_idx64;                 // 1 if indices are int64

// ---------------------------------------------------------------------------
// dtype probe: node ids < 2^31, so int64 => every odd 32-bit word is zero.
// ---------------------------------------------------------------------------
__global__ void detect_kernel(const void* __restrict__ edge_index) {
    const int* w = (const int*)edge_index;
    int all_zero = 1;
    #pragma unroll
    for (int i = 1; i < 128; i += 2) all_zero &= (w[i] == 0);
    d_idx64 = all_zero;
}

__device__ __forceinline__ int load_idx(const void* p, long long i, int idx64) {
    return idx64 ? (int)((const long long*)p)[i] : ((const int*)p)[i];
}

// ---------------------------------------------------------------------------
// zero node sums + counters
// ---------------------------------------------------------------------------
__global__ void zero_kernel() {
    int i = blockIdx.x * blockDim.x + threadIdx.x;
    const int nf4 = NG * DIM / 4;            // 32768 float4
    if (i < nf4) ((float4*)d_nodesum)[i] = make_float4(0.f, 0.f, 0.f, 0.f);
    if (i < NG) { d_ncnt[i] = 0u; d_gcnt[i] = 0u; }
}

// ---------------------------------------------------------------------------
// Pass 1: edge -> graph id, plus per-graph edge histogram (smem-privatized)
// ---------------------------------------------------------------------------
__global__ void __launch_bounds__(256) eg_kernel(
        const void* __restrict__ edge_index,
        const void* __restrict__ batch,
        int n_edges) {
    __shared__ unsigned hist[NG];
    int tid = threadIdx.x;
    for (int i = tid; i < NG; i += 256) hist[i] = 0u;
    __syncthreads();

    int idx64 = d_idx64;
    int stride = gridDim.x * 256;
    for (int e = blockIdx.x * 256 + tid; e < n_edges; e += stride) {
        int src = load_idx(edge_index, e, idx64);   // row 0 of edge_index
        int g   = load_idx(batch, src, idx64);
        d_eg[e] = g;
        atomicAdd(&hist[g], 1u);
    }
    __syncthreads();
    for (int i = tid; i < NG; i += 256)
        if (hist[i]) atomicAdd(&d_gcnt[i], hist[i]);
}

// ---------------------------------------------------------------------------
// Pass 2a: exclusive scan of edge counts (single block, 1024 threads)
// ---------------------------------------------------------------------------
__global__ void scan_kernel() {
    __shared__ unsigned t[NG];
    int i = threadIdx.x;
    unsigned v = d_gcnt[i];
    t[i] = v;
    __syncthreads();
    for (int off = 1; off < NG; off <<= 1) {
        unsigned add = (i >= off) ? t[i - off] : 0u;
        __syncthreads();
        t[i] += add;
        __syncthreads();
    }
    unsigned excl = t[i] - v;
    d_goff[i] = excl;
    d_gpos[i] = excl;
}

// ---------------------------------------------------------------------------
// Pass 2b: scatter edge ids into per-graph buckets
// ---------------------------------------------------------------------------
__global__ void scatter_kernel(int n_edges) {
    int e = blockIdx.x * blockDim.x + threadIdx.x;
    if (e >= n_edges) return;
    int g = d_eg[e];
    unsigned p = atomicAdd(&d_gpos[g], 1u);
    d_bucket[p] = e;
}

// ---------------------------------------------------------------------------
// Pass 3: atomic-free edge mean. One block per graph, warp per edge row.
// ---------------------------------------------------------------------------
__global__ void __launch_bounds__(256) esum_kernel(const float* __restrict__ edge_attr) {
    int g    = blockIdx.x;
    int lane = threadIdx.x & 31;
    int w    = threadIdx.x >> 5;

    int s = (int)d_goff[g];
    int n = (int)d_gcnt[g];

    const float4* ea = (const float4*)edge_attr;
    float4 acc = make_float4(0.f, 0.f, 0.f, 0.f);

    // double-buffered id prefetch so row loads stay independent
    int j = w;
    int e_cur = (j < n) ? d_bucket[s + j] : 0;
    for (; j < n; j += 8) {
        int jn = j + 8;
        int e_nxt = (jn < n) ? d_bucket[s + jn] : 0;
        float4 v = ea[(size_t)e_cur * 32 + lane];
        acc.x += v.x; acc.y += v.y; acc.z += v.z; acc.w += v.w;
        e_cur = e_nxt;
    }

    __shared__ float4 sacc[8][32];
    sacc[w][lane] = acc;
    __syncthreads();
    if (w == 0) {
        float4 t = sacc[0][lane];
        #pragma unroll
        for (int i = 1; i < 8; i++) {
            float4 q = sacc[i][lane];
            t.x += q.x; t.y += q.y; t.z += q.z; t.w += q.w;
        }
        float inv = 1.0f / (float)(n > 0 ? n : 1);
        t.x *= inv; t.y *= inv; t.z *= inv; t.w *= inv;
        ((float4*)(d_edge_mean + (size_t)g * DIM))[lane] = t;
    }
}

// ---------------------------------------------------------------------------
// Node sums: batch sorted -> warp owns 16-node contiguous chunk,
// run-accumulates in registers, one red.v4 per graph-run.
// ---------------------------------------------------------------------------
#define NCHUNK 16
__global__ void __launch_bounds__(256) node_kernel(
        const float* __restrict__ x,
        const void* __restrict__ batch,
        int n_nodes) {
    int idx64 = d_idx64;
    int lane  = threadIdx.x & 31;
    int warpg = (blockIdx.x * blockDim.x + threadIdx.x) >> 5;

    int s = warpg * NCHUNK;
    if (s >= n_nodes) return;
    int e = s + NCHUNK;
    if (e > n_nodes) e = n_nodes;

    const float4* xr = (const float4*)x;
    float4 acc = make_float4(0.f, 0.f, 0.f, 0.f);
    int cur_g = load_idx(batch, s, idx64);
    unsigned runc = 0;

    for (int i = s; i < e; i++) {
        int g = load_idx(batch, i, idx64);
        if (g != cur_g) {
            float* dst = d_nodesum + (size_t)cur_g * DIM + lane * 4;
            asm volatile("red.global.add.v4.f32 [%0], {%1,%2,%3,%4};"
                         :: "l"(dst), "f"(acc.x), "f"(acc.y), "f"(acc.z), "f"(acc.w)
                         : "memory");
            if (lane == 0) atomicAdd(&d_ncnt[cur_g], runc);
            acc = make_float4(0.f, 0.f, 0.f, 0.f);
            runc = 0;
            cur_g = g;
        }
        float4 v = xr[(size_t)i * 32 + lane];
        acc.x += v.x; acc.y += v.y; acc.z += v.z; acc.w += v.w;
        runc++;
    }
    float* dst = d_nodesum + (size_t)cur_g * DIM + lane * 4;
    asm volatile("red.global.add.v4.f32 [%0], {%1,%2,%3,%4};"
                 :: "l"(dst), "f"(acc.x), "f"(acc.y), "f"(acc.z), "f"(acc.w)
                 : "memory");
    if (lane == 0) atomicAdd(&d_ncnt[cur_g], runc);
}

// ---------------------------------------------------------------------------
// MLP + residual + LayerNorm. 128 blocks x 8 graphs, 256 threads.
// ---------------------------------------------------------------------------
__global__ void __launch_bounds__(256) mlp_kernel(
        const float* __restrict__ u,
        const float* __restrict__ W1, const float* __restrict__ b1,
        const float* __restrict__ W2, const float* __restrict__ b2,
        const float* __restrict__ gamma, const float* __restrict__ beta,
        float* __restrict__ out) {
    __shared__ float inp[8][3 * DIM];   // [u | edge_mean | node_mean]
    __shared__ float hbuf[8][HID];
    __shared__ float ysm[8][DIM];

    int tid = threadIdx.x;
    int g0  = blockIdx.x * 8;

    // build input rows
    for (int idx = tid; idx < 8 * DIM; idx += 256) {
        int g = idx >> 7, d = idx & (DIM - 1);
        int gg = g0 + g;
        unsigned nc = d_ncnt[gg];
        float ninv = 1.0f / (float)(nc > 0u ? nc : 1u);
        inp[g][d]           = u[(size_t)gg * DIM + d];
        inp[g][DIM + d]     = d_edge_mean[(size_t)gg * DIM + d];
        inp[g][2 * DIM + d] = d_nodesum[(size_t)gg * DIM + d] * ninv;
    }
    __syncthreads();

    // ---- layer 1: h = relu(inp @ W1 + b1), W1: [384, 512] row-major ----
    {
        float acc0[8], acc1[8];
        float bb0 = b1[tid], bb1 = b1[tid + 256];
        #pragma unroll
        for (int g = 0; g < 8; g++) { acc0[g] = bb0; acc1[g] = bb1; }

        for (int k = 0; k < 3 * DIM; k += 4) {
            float4 iv[8];
            #pragma unroll
            for (int g = 0; g < 8; g++) iv[g] = *(const float4*)&inp[g][k];
            #pragma unroll
            for (int kk = 0; kk < 4; kk++) {
                float w0 = W1[(size_t)(k + kk) * HID + tid];
                float w1 = W1[(size_t)(k + kk) * HID + tid + 256];
                #pragma unroll
                for (int g = 0; g < 8; g++) {
                    float xv = (kk == 0) ? iv[g].x : (kk == 1) ? iv[g].y
                             : (kk == 2) ? iv[g].z : iv[g].w;
                    acc0[g] = fmaf(xv, w0, acc0[g]);
                    acc1[g] = fmaf(xv, w1, acc1[g]);
                }
            }
        }
        #pragma unroll
        for (int g = 0; g < 8; g++) {
            hbuf[g][tid]       = fmaxf(acc0[g], 0.f);
            hbuf[g][tid + 256] = fmaxf(acc1[g], 0.f);
        }
    }
    __syncthreads();

    // ---- layer 2: y = h @ W2 + b2, W2: [512, 128] row-major ----
    {
        int g  = tid >> 5;
        int d0 = (tid & 31) * 4;
        float4 acc = *(const float4*)&b2[d0];
        for (int k = 0; k < HID; k++) {
            float hv = hbuf[g][k];
            float4 w = *(const float4*)&W2[(size_t)k * DIM + d0];
            acc.x = fmaf(hv, w.x, acc.x);
            acc.y = fmaf(hv, w.y, acc.y);
            acc.z = fmaf(hv, w.z, acc.z);
            acc.w = fmaf(hv, w.w, acc.w);
        }
        *(float4*)&ysm[g][d0] = acc;
    }
    __syncthreads();

    // ---- residual + layernorm: warp w handles graph w ----
    {
        int w = tid >> 5, lane = tid & 31;
        int gg = g0 + w;
        float4 v  = *(const float4*)&ysm[w][lane * 4];
        float4 uu = *(const float4*)&u[(size_t)gg * DIM + lane * 4];
        v.x += uu.x; v.y += uu.y; v.z += uu.z; v.w += uu.w;

        float s = v.x + v.y + v.z + v.w;
        #pragma unroll
        for (int off = 16; off; off >>= 1) s += __shfl_xor_sync(0xffffffffu, s, off);
        float mu = s * (1.0f / DIM);

        float dx = v.x - mu, dy = v.y - mu, dz = v.z - mu, dw = v.w - mu;
        float sq = dx * dx + dy * dy + dz * dz + dw * dw;
        #pragma unroll
        for (int off = 16; off; off >>= 1) sq += __shfl_xor_sync(0xffffffffu, sq, off);
        float rs = rsqrtf(sq * (1.0f / DIM) + 1e-5f);

        float4 gm = *(const float4*)&gamma[lane * 4];
        float4 bt = *(const float4*)&beta[lane * 4];
        float4 o;
        o.x = dx * rs * gm.x + bt.x;
        o.y = dy * rs * gm.y + bt.y;
        o.z = dz * rs * gm.z + bt.z;
        o.w = dw * rs * gm.w + bt.w;
        *(float4*)&out[(size_t)gg * DIM + lane * 4] = o;
    }
}

// ---------------------------------------------------------------------------
extern "C" void kernel_launch(void* const* d_in, const int* in_sizes, int n_in,
                              void* d_out, int out_size) {
    const float* x         = (const float*)d_in[0];
    const float* edge_attr = (const float*)d_in[1];
    const float* u         = (const float*)d_in[2];
    const float* W1        = (const float*)d_in[3];
    const float* b1        = (const float*)d_in[4];
    const float* W2        = (const float*)d_in[5];
    const float* b2        = (const float*)d_in[6];
    const float* gamma     = (const float*)d_in[7];
    const float* beta      = (const float*)d_in[8];
    const void* edge_index = d_in[9];
    const void* batch      = d_in[10];

    int n_edges = in_sizes[9] / 2;
    int n_nodes = in_sizes[10];
    float* out = (float*)d_out;

    detect_kernel<<<1, 1>>>(edge_index);
    zero_kernel<<<128, 256>>>();
    eg_kernel<<<148, 256>>>(edge_index, batch, n_edges);
    node_kernel<<<(n_nodes + NCHUNK * 8 - 1) / (NCHUNK * 8), 256>>>(x, batch, n_nodes);
    scan_kernel<<<1, NG>>>();
    scatter_kernel<<<(n_edges + 255) / 256, 256>>>(n_edges);
    esum_kernel<<<NG, 256>>>(edge_attr);
    mlp_kernel<<<NG / 8, 256>>>(u, W1, b1, W2, b2, gamma, beta, out);
}

// round 4
// speedup vs baseline: 1.0694x; 1.0694x over previous
#include <cuda_runtime.h>
#include <cstdint>

#define NG    1024
#define DIM   128
#define HID   512
#define MAXE  500000
#define NB    148          // sort kernel grid (1 block per SM)

// ---- scratch (no allocations allowed) ----
__device__ float    d_edge_mean[NG * DIM];     // per-graph edge mean
__device__ float    d_nodesum[NG * DIM];       // per-graph node sums (red target)
__device__ unsigned d_ncnt[NG];                // node counts
__device__ unsigned d_gcnt[NG];                // edge counts per graph
__device__ unsigned d_goff[NG];                // bucket start offsets
__device__ unsigned d_h[NB * NG];              // per-block histograms -> offsets
__device__ int      d_eg[MAXE];                // graph id per edge
__device__ int      d_bucket[MAXE];            // edge ids grouped by graph
__device__ volatile unsigned d_bar_gen;        // grid barrier generation (monotonic)
__device__ unsigned d_bar_cnt;                 // grid barrier arrival count

// ---------------------------------------------------------------------------
__device__ __forceinline__ int load_idx(const void* p, long long i, int idx64) {
    return idx64 ? (int)((const long long*)p)[i] : ((const int*)p)[i];
}

// per-block dtype probe on edge_index: node ids are random nonzero ints, so
// all-zero odd 32-bit words  <=>  int64 storage.
__device__ __forceinline__ int probe_idx64(const void* edge_index) {
    const int* w = (const int*)edge_index;
    int all_zero = 1;
    #pragma unroll
    for (int i = 1; i < 128; i += 2) all_zero &= (w[i] == 0);
    return all_zero;
}

// software grid barrier (all NB blocks resident: NB == #SMs)
__device__ __forceinline__ void gbar() {
    __syncthreads();
    if (threadIdx.x == 0) {
        unsigned g = d_bar_gen;
        __threadfence();
        if (atomicAdd(&d_bar_cnt, 1u) == NB - 1) {
            d_bar_cnt = 0;
            __threadfence();
            d_bar_gen = g + 1;
        } else {
            while (d_bar_gen == g) { }
            __threadfence();
        }
    }
    __syncthreads();
}

// ---------------------------------------------------------------------------
// zero counters + node sums
// ---------------------------------------------------------------------------
__global__ void zero_kernel() {
    int i = blockIdx.x * blockDim.x + threadIdx.x;
    const int nf4 = NG * DIM / 4;
    if (i < nf4) ((float4*)d_nodesum)[i] = make_float4(0.f, 0.f, 0.f, 0.f);
    if (i < NG) { d_ncnt[i] = 0u; d_gcnt[i] = 0u; }
}

// ---------------------------------------------------------------------------
// Fused counting sort of edges by graph id.
//   phase 1: per-block histogram + d_eg
//   phase 2: block 0 scans gcnt -> goff
//   phase 3: per-(block,graph) offsets (in-place over d_h)
//   phase 4: order-preserving scatter into d_bucket
// ---------------------------------------------------------------------------
__global__ void __launch_bounds__(256) sort_kernel(
        const void* __restrict__ edge_index,
        const void* __restrict__ batch,
        int n_edges) {
    __shared__ unsigned s_arr[NG];
    __shared__ unsigned s_w[256];
    __shared__ int s_idx64;

    int tid = threadIdx.x;
    int b   = blockIdx.x;

    if (tid == 0) s_idx64 = probe_idx64(edge_index);
    for (int i = tid; i < NG; i += 256) s_arr[i] = 0u;
    __syncthreads();
    int idx64 = s_idx64;

    int epb = (n_edges + NB - 1) / NB;
    int e0  = b * epb;
    int e1  = e0 + epb; if (e1 > n_edges) e1 = n_edges;

    // phase 1: histogram + graph ids
    for (int e = e0 + tid; e < e1; e += 256) {
        int src = load_idx(edge_index, e, idx64);   // row 0 of edge_index
        int g   = load_idx(batch, src, idx64);
        d_eg[e] = g;
        atomicAdd(&s_arr[g], 1u);
    }
    __syncthreads();
    for (int i = tid; i < NG; i += 256) {
        unsigned v = s_arr[i];
        d_h[b * NG + i] = v;
        if (v) atomicAdd(&d_gcnt[i], v);
    }
    gbar();

    // phase 2: block 0 scans the 1024 counts
    if (b == 0) {
        for (int i = tid; i < NG; i += 256) s_arr[i] = d_gcnt[i];
        __syncthreads();
        unsigned a0 = s_arr[tid * 4], a1 = s_arr[tid * 4 + 1],
                 a2 = s_arr[tid * 4 + 2], a3 = s_arr[tid * 4 + 3];
        unsigned ts = a0 + a1 + a2 + a3;
        s_w[tid] = ts;
        __syncthreads();
        for (int off = 1; off < 256; off <<= 1) {
            unsigned add = (tid >= off) ? s_w[tid - off] : 0u;
            __syncthreads();
            s_w[tid] += add;
            __syncthreads();
        }
        unsigned base = s_w[tid] - ts;
        d_goff[tid * 4]     = base;
        d_goff[tid * 4 + 1] = base + a0;
        d_goff[tid * 4 + 2] = base + a0 + a1;
        d_goff[tid * 4 + 3] = base + a0 + a1 + a2;
    }
    gbar();

    // phase 3: in-place column scan of d_h: h[b][g] <- goff[g] + sum_{b'<b} h[b'][g]
    {
        int t = b * 256 + tid;
        if (t < NG) {
            unsigned running = d_goff[t];
            for (int b2 = 0; b2 < NB; b2++) {
                unsigned v = d_h[b2 * NG + t];
                d_h[b2 * NG + t] = running;
                running += v;
            }
        }
    }
    gbar();

    // phase 4: scatter (block-order preserving -> near-sorted buckets)
    for (int i = tid; i < NG; i += 256) s_arr[i] = 0u;
    __syncthreads();
    for (int e = e0 + tid; e < e1; e += 256) {
        int g = d_eg[e];
        unsigned pos = d_h[b * NG + g] + atomicAdd(&s_arr[g], 1u);
        d_bucket[pos] = e;
    }
}

// ---------------------------------------------------------------------------
// Node sums: batch sorted -> warp owns 16-node chunk, run-accumulate,
// one red.v4 per graph-run.
// ---------------------------------------------------------------------------
#define NCHUNK 16
__global__ void __launch_bounds__(256) node_kernel(
        const float* __restrict__ x,
        const void* __restrict__ batch,
        const void* __restrict__ edge_index,   // for dtype probe only
        int n_nodes) {
    __shared__ int s_idx64;
    if (threadIdx.x == 0) s_idx64 = probe_idx64(edge_index);
    __syncthreads();
    int idx64 = s_idx64;

    int lane  = threadIdx.x & 31;
    int warpg = (blockIdx.x * blockDim.x + threadIdx.x) >> 5;

    int s = warpg * NCHUNK;
    if (s >= n_nodes) return;
    int e = s + NCHUNK;
    if (e > n_nodes) e = n_nodes;

    const float4* xr = (const float4*)x;
    float4 acc = make_float4(0.f, 0.f, 0.f, 0.f);
    int cur_g = load_idx(batch, s, idx64);
    unsigned runc = 0;

    for (int i = s; i < e; i++) {
        int g = load_idx(batch, i, idx64);
        if (g != cur_g) {
            float* dst = d_nodesum + (size_t)cur_g * DIM + lane * 4;
            asm volatile("red.global.add.v4.f32 [%0], {%1,%2,%3,%4};"
                         :: "l"(dst), "f"(acc.x), "f"(acc.y), "f"(acc.z), "f"(acc.w)
                         : "memory");
            if (lane == 0) atomicAdd(&d_ncnt[cur_g], runc);
            acc = make_float4(0.f, 0.f, 0.f, 0.f);
            runc = 0;
            cur_g = g;
        }
        float4 v = xr[(size_t)i * 32 + lane];
        acc.x += v.x; acc.y += v.y; acc.z += v.z; acc.w += v.w;
        runc++;
    }
    float* dst = d_nodesum + (size_t)cur_g * DIM + lane * 4;
    asm volatile("red.global.add.v4.f32 [%0], {%1,%2,%3,%4};"
                 :: "l"(dst), "f"(acc.x), "f"(acc.y), "f"(acc.z), "f"(acc.w)
                 : "memory");
    if (lane == 0) atomicAdd(&d_ncnt[cur_g], runc);
}

// ---------------------------------------------------------------------------
// Atomic-free edge mean: block per graph, warp handles 2 rows per iteration.
// ---------------------------------------------------------------------------
__global__ void __launch_bounds__(256) esum_kernel(const float* __restrict__ edge_attr) {
    int g    = blockIdx.x;
    int lane = threadIdx.x & 31;
    int w    = threadIdx.x >> 5;

    int s = (int)d_goff[g];
    int n = (int)d_gcnt[g];

    const float4* ea = (const float4*)edge_attr;
    float4 a0 = make_float4(0.f, 0.f, 0.f, 0.f);
    float4 a1 = make_float4(0.f, 0.f, 0.f, 0.f);

    int j  = w * 2;
    int c0 = (j     < n) ? d_bucket[s + j]     : -1;
    int c1 = (j + 1 < n) ? d_bucket[s + j + 1] : -1;
    for (; j < n; j += 16) {
        int f0 = (j + 16 < n) ? d_bucket[s + j + 16] : -1;
        int f1 = (j + 17 < n) ? d_bucket[s + j + 17] : -1;
        if (c0 >= 0) {
            float4 v = ea[(size_t)c0 * 32 + lane];
            a0.x += v.x; a0.y += v.y; a0.z += v.z; a0.w += v.w;
        }
        if (c1 >= 0) {
            float4 v = ea[(size_t)c1 * 32 + lane];
            a1.x += v.x; a1.y += v.y; a1.z += v.z; a1.w += v.w;
        }
        c0 = f0; c1 = f1;
    }
    a0.x += a1.x; a0.y += a1.y; a0.z += a1.z; a0.w += a1.w;

    __shared__ float4 sacc[8][32];
    sacc[w][lane] = a0;
    __syncthreads();
    if (w == 0) {
        float4 t = sacc[0][lane];
        #pragma unroll
        for (int i = 1; i < 8; i++) {
            float4 q = sacc[i][lane];
            t.x += q.x; t.y += q.y; t.z += q.z; t.w += q.w;
        }
        float inv = 1.0f / (float)(n > 0 ? n : 1);
        t.x *= inv; t.y *= inv; t.z *= inv; t.w *= inv;
        ((float4*)(d_edge_mean + (size_t)g * DIM))[lane] = t;
    }
}

// ---------------------------------------------------------------------------
// MLP + residual + LayerNorm. 128 blocks x 8 graphs, 256 threads.
// ---------------------------------------------------------------------------
__global__ void __launch_bounds__(256) mlp_kernel(
        const float* __restrict__ u,
        const float* __restrict__ W1, const float* __restrict__ b1,
        const float* __restrict__ W2, const float* __restrict__ b2,
        const float* __restrict__ gamma, const float* __restrict__ beta,
        float* __restrict__ out) {
    __shared__ float inp[8][3 * DIM];
    __shared__ float hbuf[8][HID];
    __shared__ float ysm[8][DIM];

    int tid = threadIdx.x;
    int g0  = blockIdx.x * 8;

    for (int idx = tid; idx < 8 * DIM; idx += 256) {
        int g = idx >> 7, d = idx & (DIM - 1);
        int gg = g0 + g;
        unsigned nc = d_ncnt[gg];
        float ninv = 1.0f / (float)(nc > 0u ? nc : 1u);
        inp[g][d]           = u[(size_t)gg * DIM + d];
        inp[g][DIM + d]     = d_edge_mean[(size_t)gg * DIM + d];
        inp[g][2 * DIM + d] = d_nodesum[(size_t)gg * DIM + d] * ninv;
    }
    __syncthreads();

    // layer 1
    {
        float acc0[8], acc1[8];
        float bb0 = b1[tid], bb1 = b1[tid + 256];
        #pragma unroll
        for (int g = 0; g < 8; g++) { acc0[g] = bb0; acc1[g] = bb1; }

        for (int k = 0; k < 3 * DIM; k += 4) {
            float4 iv[8];
            #pragma unroll
            for (int g = 0; g < 8; g++) iv[g] = *(const float4*)&inp[g][k];
            #pragma unroll
            for (int kk = 0; kk < 4; kk++) {
                float w0 = W1[(size_t)(k + kk) * HID + tid];
                float w1 = W1[(size_t)(k + kk) * HID + tid + 256];
                #pragma unroll
                for (int g = 0; g < 8; g++) {
                    float xv = (kk == 0) ? iv[g].x : (kk == 1) ? iv[g].y
                             : (kk == 2) ? iv[g].z : iv[g].w;
                    acc0[g] = fmaf(xv, w0, acc0[g]);
                    acc1[g] = fmaf(xv, w1, acc1[g]);
                }
            }
        }
        #pragma unroll
        for (int g = 0; g < 8; g++) {
            hbuf[g][tid]       = fmaxf(acc0[g], 0.f);
            hbuf[g][tid + 256] = fmaxf(acc1[g], 0.f);
        }
    }
    __syncthreads();

    // layer 2
    {
        int g  = tid >> 5;
        int d0 = (tid & 31) * 4;
        float4 acc = *(const float4*)&b2[d0];
        for (int k = 0; k < HID; k++) {
            float hv = hbuf[g][k];
            float4 w = *(const float4*)&W2[(size_t)k * DIM + d0];
            acc.x = fmaf(hv, w.x, acc.x);
            acc.y = fmaf(hv, w.y, acc.y);
            acc.z = fmaf(hv, w.z, acc.z);
            acc.w = fmaf(hv, w.w, acc.w);
        }
        *(float4*)&ysm[g][d0] = acc;
    }
    __syncthreads();

    // residual + layernorm
    {
        int w = tid >> 5, lane = tid & 31;
        int gg = g0 + w;
        float4 v  = *(const float4*)&ysm[w][lane * 4];
        float4 uu = *(const float4*)&u[(size_t)gg * DIM + lane * 4];
        v.x += uu.x; v.y += uu.y; v.z += uu.z; v.w += uu.w;

        float sm = v.x + v.y + v.z + v.w;
        #pragma unroll
        for (int off = 16; off; off >>= 1) sm += __shfl_xor_sync(0xffffffffu, sm, off);
        float mu = sm * (1.0f / DIM);

        float dx = v.x - mu, dy = v.y - mu, dz = v.z - mu, dw = v.w - mu;
        float sq = dx * dx + dy * dy + dz * dz + dw * dw;
        #pragma unroll
        for (int off = 16; off; off >>= 1) sq += __shfl_xor_sync(0xffffffffu, sq, off);
        float rs = rsqrtf(sq * (1.0f / DIM) + 1e-5f);

        float4 gm = *(const float4*)&gamma[lane * 4];
        float4 bt = *(const float4*)&beta[lane * 4];
        float4 o;
        o.x = dx * rs * gm.x + bt.x;
        o.y = dy * rs * gm.y + bt.y;
        o.z = dz * rs * gm.z + bt.z;
        o.w = dw * rs * gm.w + bt.w;
        *(float4*)&out[(size_t)gg * DIM + lane * 4] = o;
    }
}

// ---------------------------------------------------------------------------
extern "C" void kernel_launch(void* const* d_in, const int* in_sizes, int n_in,
                              void* d_out, int out_size) {
    const float* x         = (const float*)d_in[0];
    const float* edge_attr = (const float*)d_in[1];
    const float* u         = (const float*)d_in[2];
    const float* W1        = (const float*)d_in[3];
    const float* b1        = (const float*)d_in[4];
    const float* W2        = (const float*)d_in[5];
    const float* b2        = (const float*)d_in[6];
    const float* gamma     = (const float*)d_in[7];
    const float* beta      = (const float*)d_in[8];
    const void* edge_index = d_in[9];
    const void* batch      = d_in[10];

    int n_edges = in_sizes[9] / 2;
    int n_nodes = in_sizes[10];
    float* out = (float*)d_out;

    zero_kernel<<<128, 256>>>();                                               // 1
    sort_kernel<<<NB, 256>>>(edge_index, batch, n_edges);                      // 2
    node_kernel<<<(n_nodes + NCHUNK * 8 - 1) / (NCHUNK * 8), 256>>>(           // 3
        x, batch, edge_index, n_nodes);
    esum_kernel<<<NG, 256>>>(edge_attr);                                       // 4 <- ncu slot
    mlp_kernel<<<NG / 8, 256>>>(u, W1, b1, W2, b2, gamma, beta, out);          // 5
}